// round 6
// baseline (speedup 1.0000x reference)
#include <cuda_runtime.h>
#include <cuda_bf16.h>
#include <cstdint>
#include <math.h>

#define NQ 16384
#define NS 8192
#define D 64
#define NTILES 64
#define STEPS 10
#define NCTA 128
#define THREADS 512

// smem float offsets
#define C_OFF   8192            // c state [128][64]
#define OX_OFF  16384           // combine scratch [128][64]
#define LX_OFF  24576           // combine row sums [128]
#define BUF_OFF 24704           // 2 x 16384 u32 tile buffers
#define SMEM_FLOATS (BUF_OFF + 2 * 16384)   // 57472 floats = 229888 B

// ---------------- device globals ---------------------------------------------
__device__ float g_gx[NQ * 256];           // [q][u*4+gate]  (i,f,g,o)
__device__ float g_WihT[64 * 256];         // [d][row]
__device__ float g_Whh4[64 * 64 * 4];      // [d][u][gate]
// per tile 64KB: I1h 4096 u32 | I1l 4096 u32 | V 8192 f32 (tf32, pi-permuted)
__device__ __align__(16) uint32_t g_T[(size_t)NTILES * 16384];

// ---------------- helpers ------------------------------------------------------
__device__ __forceinline__ uint32_t smem_u32(const void* p) {
    uint32_t a;
    asm("{ .reg .u64 t; cvta.to.shared.u64 t, %1; cvt.u32.u64 %0, t; }"
        : "=r"(a) : "l"(p));
    return a;
}
__device__ __forceinline__ void cp16(uint32_t saddr, const void* g) {
    asm volatile("cp.async.cg.shared.global [%0], [%1], 16;"
                 :: "r"(saddr), "l"(g) : "memory");
}
#define CP_COMMIT() asm volatile("cp.async.commit_group;" ::: "memory")
#define CP_WAIT1()  asm volatile("cp.async.wait_group 1;" ::: "memory")

__device__ __forceinline__ float tf32f(float v) {
    float r;
    asm("cvt.rna.tf32.f32 %0, %1;" : "=f"(r) : "f"(v));
    return r;
}
__device__ __forceinline__ uint32_t bfpack(float lo, float hi) {
    __nv_bfloat162 t = __floats2bfloat162_rn(lo, hi);
    return *reinterpret_cast<uint32_t*>(&t);
}
__device__ __forceinline__ void bfsplit(float v0, float v1,
                                        uint32_t& hi, uint32_t& lo) {
    hi = bfpack(v0, v1);
    float h0 = __uint_as_float(hi << 16);
    float h1 = __uint_as_float(hi & 0xffff0000u);
    lo = bfpack(v0 - h0, v1 - h1);
}
__device__ __forceinline__ void mmabf(float* c, const uint32_t* a,
                                      uint32_t b0, uint32_t b1) {
    asm volatile(
        "mma.sync.aligned.m16n8k16.row.col.f32.bf16.bf16.f32 "
        "{%0,%1,%2,%3}, {%4,%5,%6,%7}, {%8,%9}, {%0,%1,%2,%3};"
        : "+f"(c[0]), "+f"(c[1]), "+f"(c[2]), "+f"(c[3])
        : "r"(a[0]), "r"(a[1]), "r"(a[2]), "r"(a[3]), "r"(b0), "r"(b1));
}
__device__ __forceinline__ void mmatf(float* c, float a0, float a1, float a2,
                                      float a3, float b0, float b1) {
    asm volatile(
        "mma.sync.aligned.m16n8k8.row.col.f32.tf32.tf32.f32 "
        "{%0,%1,%2,%3}, {%4,%5,%6,%7}, {%8,%9}, {%0,%1,%2,%3};"
        : "+f"(c[0]), "+f"(c[1]), "+f"(c[2]), "+f"(c[3])
        : "r"(__float_as_uint(a0)), "r"(__float_as_uint(a1)),
          "r"(__float_as_uint(a2)), "r"(__float_as_uint(a3)),
          "r"(__float_as_uint(b0)), "r"(__float_as_uint(b1)));
}
__device__ __forceinline__ float sigf(float x) { return 1.f / (1.f + __expf(-x)); }

// ---------------- prep: support images ----------------------------------------
__global__ void prep_kernel(const float* __restrict__ support) {
    int t = blockIdx.x;
    const float* s = support + (size_t)t * 128 * D;
    uint32_t* dst = g_T + (size_t)t * 16384;
    // I1 (bf16 hi/lo) for MMA1: u32[ks(4)][row(128)][pairpos(8)]
    for (int i = threadIdx.x; i < 4096; i += 256) {
        int ks = i >> 10, rem = i & 1023, r = rem >> 3, p = rem & 7;
        int fp = (p & 1) ? ((p >> 1) + 4) : (p >> 1);
        int f0 = ks * 16 + fp * 2;
        uint32_t hi, lo;
        bfsplit(s[r * 64 + f0], s[r * 64 + f0 + 1], hi, lo);
        dst[i] = hi;
        dst[4096 + i] = lo;
    }
    // V (tf32) for MMA2: f32[j(8)][h(2)][k(8)][fsw(64)],
    //   row = 16j + 8h + pi(k), pi(k) = k<4 ? 2k : 2(k-4)+1, fsw = f ^ ((k&3)<<3)
    float* vd = (float*)(dst + 8192);
    for (int i = threadIdx.x; i < 8192; i += 256) {
        int j = i >> 10, h = (i >> 9) & 1, k = (i >> 6) & 7, fsw = i & 63;
        int f = fsw ^ ((k & 3) << 3);
        int pk = (k < 4) ? (2 * k) : (2 * (k - 4) + 1);
        int row = j * 16 + h * 8 + pk;
        vd[i] = tf32f(s[row * 64 + f]);
    }
}

// ---------------- weight prep + gx (once) --------------------------------------
__global__ void transpose_kernel(const float* __restrict__ W_ih,
                                 const float* __restrict__ W_hh) {
    int i = blockIdx.x * blockDim.x + threadIdx.x;
    if (i < 256 * 64) {
        int r = i / D, d = i % D;          // r: gate-major row (i,f,g,o)
        g_WihT[d * 256 + r] = W_ih[i];
        g_Whh4[(d * 64 + (r & 63)) * 4 + (r >> 6)] = W_hh[i];
    }
}
__global__ void gx_kernel(const float* __restrict__ q,
                          const float* __restrict__ b_ih,
                          const float* __restrict__ b_hh) {
    __shared__ float qs[D];
    int qi = blockIdx.x, g = threadIdx.x;
    if (g < D) qs[g] = q[qi * D + g];
    __syncthreads();
    float acc = b_ih[g] + b_hh[g];
#pragma unroll
    for (int d = 0; d < D; d++)
        acc = fmaf(qs[d], __ldg(&g_WihT[d * 256 + g]), acc);
    g_gx[qi * 256 + (g & 63) * 4 + (g >> 6)] = acc;   // [q][u][gate]
}

// ---------------- persistent fused kernel --------------------------------------
__global__ void __launch_bounds__(THREADS, 1)
fused_kernel(const float* __restrict__ q, float* __restrict__ out) {
    extern __shared__ float sm[];
    float* Hs = sm;                 // h (then z) [128][64]
    float* Cs = sm + C_OFF;         // c state [128][64]
    float* Ox = sm + OX_OFF;
    float* lx = sm + LX_OFF;
    const int tid = threadIdx.x;
    const int w = tid >> 5, lane = tid & 31;
    const int g = lane >> 2, qq = lane & 3;
    const int wq = w & 7, jo = w >> 3;
    const int mrow = wq * 16;
    const int qbase = blockIdx.x * 128;
    const uint32_t sb = smem_u32(sm);

    // init: Hs = q, c = 0
    {
        const float4* qp = (const float4*)(q + (size_t)qbase * D);
        float4* H4 = (float4*)Hs;
        float4* C4 = (float4*)Cs;
        for (int i = tid; i < 2048; i += THREADS) {
            H4[i] = qp[i];
            C4[i] = make_float4(0.f, 0.f, 0.f, 0.f);
        }
    }
    // prefetch tiles 0,1 (64KB each)
    {
        const char* src = (const char*)g_T + tid * 16;
        uint32_t dst = sb + BUF_OFF * 4 + tid * 16;
#pragma unroll
        for (int i = 0; i < 8; i++) cp16(dst + i * 8192, src + i * 8192);
        CP_COMMIT();
#pragma unroll
        for (int i = 0; i < 8; i++)
            cp16(dst + 65536 + i * 8192, src + 65536 + i * 8192);
        CP_COMMIT();
    }
    __syncthreads();

    const int joff = (w >> 2) & 3;

    for (int step = 0; step < STEPS; step++) {
        const int last = (step == STEPS - 1);

        // ---- A fragments (bf16 hi/lo) from Hs
        uint32_t ahi[16], alo[16];
        {
            int row0 = mrow + g, row1 = mrow + g + 8;
#pragma unroll
            for (int ks = 0; ks < 4; ks++) {
                int cb = ks * 16 + 2 * qq;
                bfsplit(Hs[row0 * 64 + cb],     Hs[row0 * 64 + cb + 1],
                        ahi[4 * ks + 0], alo[4 * ks + 0]);
                bfsplit(Hs[row1 * 64 + cb],     Hs[row1 * 64 + cb + 1],
                        ahi[4 * ks + 1], alo[4 * ks + 1]);
                bfsplit(Hs[row0 * 64 + cb + 8], Hs[row0 * 64 + cb + 9],
                        ahi[4 * ks + 2], alo[4 * ks + 2]);
                bfsplit(Hs[row1 * 64 + cb + 8], Hs[row1 * 64 + cb + 9],
                        ahi[4 * ks + 3], alo[4 * ks + 3]);
            }
        }

        float O[32];
#pragma unroll
        for (int i = 0; i < 32; i++) O[i] = 0.f;
        float lacc0 = 0.f, lacc1 = 0.f;

#pragma unroll 1
        for (int t = 0; t < NTILES; t++) {
            CP_WAIT1();
            __syncthreads();
            const uint32_t* B = (const uint32_t*)(sm + BUF_OFF) + (t & 1) * 16384;
            const float* V = (const float*)(B + 8192);

#pragma unroll 1
            for (int jc = 0; jc < 4; jc++) {
                int j = jo + 2 * ((joff + jc) & 3);
                // ---- MMA1: S[16q x 16s], 3-term bf16 split
                float c0h[4] = {0, 0, 0, 0}, c0x[4] = {0, 0, 0, 0}, c0y[4] = {0, 0, 0, 0};
                float c1h[4] = {0, 0, 0, 0}, c1x[4] = {0, 0, 0, 0}, c1y[4] = {0, 0, 0, 0};
                int r0 = 16 * j + g;
#pragma unroll
                for (int ks = 0; ks < 4; ks++) {
                    const uint32_t* p0 = B + ks * 1024 + r0 * 8 + 2 * qq;
                    uint2 bh0 = *(const uint2*)(p0);
                    uint2 bl0 = *(const uint2*)(p0 + 4096);
                    mmabf(c0h, ahi + 4 * ks, bh0.x, bh0.y);
                    mmabf(c0x, ahi + 4 * ks, bl0.x, bl0.y);
                    mmabf(c0y, alo + 4 * ks, bh0.x, bh0.y);
                    uint2 bh1 = *(const uint2*)(p0 + 64);
                    uint2 bl1 = *(const uint2*)(p0 + 4160);
                    mmabf(c1h, ahi + 4 * ks, bh1.x, bh1.y);
                    mmabf(c1x, ahi + 4 * ks, bl1.x, bl1.y);
                    mmabf(c1y, alo + 4 * ks, bh1.x, bh1.y);
                }
                // ---- exp (constant shift = exact softmax invariance), tf32-round
                float pA0 = tf32f(__expf(c0h[0] + c0x[0] + c0y[0] - 32.f));
                float pA1 = tf32f(__expf(c0h[1] + c0x[1] + c0y[1] - 32.f));
                float pA2 = tf32f(__expf(c0h[2] + c0x[2] + c0y[2] - 32.f));
                float pA3 = tf32f(__expf(c0h[3] + c0x[3] + c0y[3] - 32.f));
                float pB0 = tf32f(__expf(c1h[0] + c1x[0] + c1y[0] - 32.f));
                float pB1 = tf32f(__expf(c1h[1] + c1x[1] + c1y[1] - 32.f));
                float pB2 = tf32f(__expf(c1h[2] + c1x[2] + c1y[2] - 32.f));
                float pB3 = tf32f(__expf(c1h[3] + c1x[3] + c1y[3] - 32.f));
                lacc0 += (pA0 + pA1) + (pB0 + pB1);
                lacc1 += (pA2 + pA3) + (pB2 + pB3);
                // ---- MMA2: O += P @ V, tf32 single-pass, pi-permuted V
                const float* Vj = V + j * 1024;
                int fbase = (2 * qq) * 64;   // reuse as k offsets below
#pragma unroll
                for (int nb0 = 0; nb0 < 8; nb0++) {
                    int nb = (nb0 + w) & 7;
                    int fsw = (nb * 8 + g) ^ (qq << 3);
                    float b00 = Vj[qq * 64 + fsw];
                    float b01 = Vj[(qq + 4) * 64 + fsw];
                    mmatf(O + 4 * nb, pA0, pA2, pA1, pA3, b00, b01);
                    float b10 = Vj[512 + qq * 64 + fsw];
                    float b11 = Vj[512 + (qq + 4) * 64 + fsw];
                    mmatf(O + 4 * nb, pB0, pB2, pB1, pB3, b10, b11);
                }
                (void)fbase;
            }
            __syncthreads();
            if (!(last && t >= NTILES - 2)) {
                int nt = (t + 2) & (NTILES - 1);
                const char* src = (const char*)g_T + (size_t)nt * 65536 + tid * 16;
                uint32_t dst = sb + BUF_OFF * 4 + (t & 1) * 65536 + tid * 16;
#pragma unroll
                for (int i = 0; i < 8; i++) cp16(dst + i * 8192, src + i * 8192);
            }
            CP_COMMIT();
        }

        // ---- combine partial O/l across jo groups; z -> Hs
        lacc0 += __shfl_xor_sync(0xffffffffu, lacc0, 1);
        lacc0 += __shfl_xor_sync(0xffffffffu, lacc0, 2);
        lacc1 += __shfl_xor_sync(0xffffffffu, lacc1, 1);
        lacc1 += __shfl_xor_sync(0xffffffffu, lacc1, 2);
        int row0 = mrow + g, row1 = row0 + 8;
        if (jo == 1) {
#pragma unroll
            for (int nb = 0; nb < 8; nb++) {
                int c = nb * 8 + 2 * qq;
                *(float2*)(Ox + row0 * 64 + c) = make_float2(O[4 * nb + 0], O[4 * nb + 1]);
                *(float2*)(Ox + row1 * 64 + c) = make_float2(O[4 * nb + 2], O[4 * nb + 3]);
            }
            if (qq == 0) { lx[row0] = lacc0; lx[row1] = lacc1; }
        }
        __syncthreads();
        if (jo == 0) {
            float inv0 = 1.f / (lacc0 + lx[row0]);
            float inv1 = 1.f / (lacc1 + lx[row1]);
#pragma unroll
            for (int nb = 0; nb < 8; nb++) {
                int c = nb * 8 + 2 * qq;
                float2 ob0 = *(const float2*)(Ox + row0 * 64 + c);
                float2 ob1 = *(const float2*)(Ox + row1 * 64 + c);
                float z00 = Hs[row0 * 64 + c]     + (O[4 * nb + 0] + ob0.x) * inv0;
                float z01 = Hs[row0 * 64 + c + 1] + (O[4 * nb + 1] + ob0.y) * inv0;
                float z10 = Hs[row1 * 64 + c]     + (O[4 * nb + 2] + ob1.x) * inv1;
                float z11 = Hs[row1 * 64 + c + 1] + (O[4 * nb + 3] + ob1.y) * inv1;
                *(float2*)(Hs + row0 * 64 + c) = make_float2(z00, z01);
                *(float2*)(Hs + row1 * 64 + c) = make_float2(z10, z11);
            }
        }
        __syncthreads();

        // ---- LSTM phase: warp w owns queries w*8..w*8+7; units lane, lane+32
        {
            const int w8 = w * 8;
            const int uA = lane, uB = lane + 32;
            float4 accA[8], accB[8];
#pragma unroll
            for (int qi = 0; qi < 8; qi++) {
                int gq = qbase + w8 + qi;
                accA[qi] = __ldg((const float4*)&g_gx[(size_t)gq * 256 + uA * 4]);
                accB[qi] = __ldg((const float4*)&g_gx[(size_t)gq * 256 + uB * 4]);
            }
#pragma unroll 2
            for (int d = 0; d < 64; d++) {
                float4 wA = __ldg((const float4*)&g_Whh4[(d * 64 + uA) * 4]);
                float4 wB = __ldg((const float4*)&g_Whh4[(d * 64 + uB) * 4]);
#pragma unroll
                for (int qi = 0; qi < 8; qi++) {
                    float zd = Hs[(w8 + qi) * 64 + d];
                    accA[qi].x = fmaf(zd, wA.x, accA[qi].x);
                    accA[qi].y = fmaf(zd, wA.y, accA[qi].y);
                    accA[qi].z = fmaf(zd, wA.z, accA[qi].z);
                    accA[qi].w = fmaf(zd, wA.w, accA[qi].w);
                    accB[qi].x = fmaf(zd, wB.x, accB[qi].x);
                    accB[qi].y = fmaf(zd, wB.y, accB[qi].y);
                    accB[qi].z = fmaf(zd, wB.z, accB[qi].z);
                    accB[qi].w = fmaf(zd, wB.w, accB[qi].w);
                }
            }
#pragma unroll
            for (int qi = 0; qi < 8; qi++) {
                int row = w8 + qi;
                int gq = qbase + row;
                // unit uA
                {
                    float4 a = accA[qi];
                    float co = Cs[row * 64 + uA];
                    float cn = sigf(a.y) * co + sigf(a.x) * tanhf(a.z);
                    float hn = sigf(a.w) * tanhf(cn);
                    Cs[row * 64 + uA] = cn;
                    float hv = hn + __ldg(&q[(size_t)gq * 64 + uA]);
                    if (last) out[(size_t)gq * 64 + uA] = hv;
                    else Hs[row * 64 + uA] = hv;
                }
                // unit uB
                {
                    float4 a = accB[qi];
                    float co = Cs[row * 64 + uB];
                    float cn = sigf(a.y) * co + sigf(a.x) * tanhf(a.z);
                    float hn = sigf(a.w) * tanhf(cn);
                    Cs[row * 64 + uB] = cn;
                    float hv = hn + __ldg(&q[(size_t)gq * 64 + uB]);
                    if (last) out[(size_t)gq * 64 + uB] = hv;
                    else Hs[row * 64 + uB] = hv;
                }
            }
        }
        __syncthreads();
    }
}

// ---------------- launch --------------------------------------------------------
extern "C" void kernel_launch(void* const* d_in, const int* in_sizes, int n_in,
                              void* d_out, int out_size) {
    const float* support = (const float*)d_in[0];
    const float* queries = (const float*)d_in[1];
    const float* W_ih    = (const float*)d_in[2];
    const float* W_hh    = (const float*)d_in[3];
    const float* b_ih    = (const float*)d_in[4];
    const float* b_hh    = (const float*)d_in[5];
    float* out = (float*)d_out;

    const int smem_bytes = SMEM_FLOATS * 4;   // 229888
    cudaFuncSetAttribute(fused_kernel, cudaFuncAttributeMaxDynamicSharedMemorySize,
                         smem_bytes);

    prep_kernel<<<NTILES, 256>>>(support);
    transpose_kernel<<<(256 * 64 + 255) / 256, 256>>>(W_ih, W_hh);
    gx_kernel<<<NQ, 256>>>(queries, b_ih, b_hh);
    fused_kernel<<<NCTA, THREADS, smem_bytes>>>(queries, out);
}

// round 7
// speedup vs baseline: 2.1120x; 2.1120x over previous
#include <cuda_runtime.h>
#include <cuda_bf16.h>
#include <cstdint>
#include <math.h>

#define NQ 16384
#define NS 8192
#define D 64
#define NTILES 64          // support tiles of 128 rows
#define STEPS 10
#define NCTA (NQ / 128)    // 128 CTAs, 16 warps each

// ---------------- device globals (no allocations allowed) -------------------
__device__ float g_hhat[NQ * D];
__device__ float g_c[NQ * D];
__device__ float g_z[NQ * D];
__device__ float g_gx[NQ * 4 * D];
__device__ float g_WihT[D * 4 * D];
__device__ float g_WhhT[D * 4 * D];
// Per tile (16384 u32 = 64KB):
//  I1: u32[term2][ks4][j8][g8][qq4][vec4]          (8192 u32)
//      vec = (b0@r0, b1@r0, b0@r8, b1@r8), r0=16j+g, r8=r0+8,
//      b0 = bf16x2 features (16ks+2qq, +1), b1 = (16ks+8+2qq, +1)
//  V : f32[j8][h2][qq4][fslot64][pr2] at +8192     (8192 f32)
//      f = fslot ^ (qq<<2); pr 0/1 -> support row 16j+8h+2qq+pr (tf32)
__device__ __align__(16) uint32_t g_B[(size_t)NTILES * 16384];

// ---------------- helpers ----------------------------------------------------
__device__ __forceinline__ uint32_t smem_u32(const void* p) {
    uint32_t a;
    asm("{ .reg .u64 t; cvta.to.shared.u64 t, %1; cvt.u32.u64 %0, t; }"
        : "=r"(a) : "l"(p));
    return a;
}
__device__ __forceinline__ void cp16(uint32_t saddr, const void* g) {
    asm volatile("cp.async.cg.shared.global [%0], [%1], 16;"
                 :: "r"(saddr), "l"(g) : "memory");
}
#define CP_COMMIT() asm volatile("cp.async.commit_group;" ::: "memory")
#define CP_WAIT1()  asm volatile("cp.async.wait_group 1;" ::: "memory")
#define CP_WAIT0()  asm volatile("cp.async.wait_group 0;" ::: "memory")

__device__ __forceinline__ float tf32f(float v) {
    float r;
    asm("cvt.rna.tf32.f32 %0, %1;" : "=f"(r) : "f"(v));
    return r;
}
__device__ __forceinline__ uint32_t bfpack(float lo, float hi) {
    __nv_bfloat162 t = __floats2bfloat162_rn(lo, hi);
    return *reinterpret_cast<uint32_t*>(&t);
}
__device__ __forceinline__ void bfsplit(float v0, float v1,
                                        uint32_t& hi, uint32_t& lo) {
    hi = bfpack(v0, v1);
    float h0 = __uint_as_float(hi << 16);
    float h1 = __uint_as_float(hi & 0xffff0000u);
    lo = bfpack(v0 - h0, v1 - h1);
}
__device__ __forceinline__ void mmabf(float* c, const uint32_t* a,
                                      uint32_t b0, uint32_t b1) {
    asm volatile(
        "mma.sync.aligned.m16n8k16.row.col.f32.bf16.bf16.f32 "
        "{%0,%1,%2,%3}, {%4,%5,%6,%7}, {%8,%9}, {%0,%1,%2,%3};"
        : "+f"(c[0]), "+f"(c[1]), "+f"(c[2]), "+f"(c[3])
        : "r"(a[0]), "r"(a[1]), "r"(a[2]), "r"(a[3]), "r"(b0), "r"(b1));
}
__device__ __forceinline__ void mmatf(float* c, float a0, float a1, float a2,
                                      float a3, float b0, float b1) {
    asm volatile(
        "mma.sync.aligned.m16n8k8.row.col.f32.tf32.tf32.f32 "
        "{%0,%1,%2,%3}, {%4,%5,%6,%7}, {%8,%9}, {%0,%1,%2,%3};"
        : "+f"(c[0]), "+f"(c[1]), "+f"(c[2]), "+f"(c[3])
        : "r"(__float_as_uint(a0)), "r"(__float_as_uint(a1)),
          "r"(__float_as_uint(a2)), "r"(__float_as_uint(a3)),
          "r"(__float_as_uint(b0)), "r"(__float_as_uint(b1)));
}
__device__ __forceinline__ float sigf(float x) { return 1.f / (1.f + __expf(-x)); }

// ---------------- prep: support images --------------------------------------
__global__ void prep_kernel(const float* __restrict__ support) {
    int t = blockIdx.x;
    const float* s = support + (size_t)t * 128 * D;
    uint32_t* dst = g_B + (size_t)t * 16384;
    // I1 (bf16 hi/lo), LDS.128-friendly
    for (int i = threadIdx.x; i < 4096; i += 256) {
        int vec = i & 3, qq = (i >> 2) & 3, g = (i >> 4) & 7;
        int j = (i >> 7) & 7, ks = (i >> 10) & 3;
        int r = 16 * j + g + ((vec & 2) ? 8 : 0);
        int f0 = ks * 16 + ((vec & 1) ? 8 : 0) + 2 * qq;
        uint32_t hi, lo;
        bfsplit(s[r * 64 + f0], s[r * 64 + f0 + 1], hi, lo);
        dst[i] = hi;
        dst[4096 + i] = lo;
    }
    // V (tf32, pi-permuted, swizzled), LDS.64-friendly
    float* vd = (float*)(dst + 8192);
    for (int i = threadIdx.x; i < 8192; i += 256) {
        int pr = i & 1, fslot = (i >> 1) & 63, qq = (i >> 7) & 3;
        int h = (i >> 9) & 1, j = (i >> 10) & 7;
        int f = fslot ^ (qq << 2);
        int row = 16 * j + 8 * h + 2 * qq + pr;
        vd[i] = tf32f(s[row * 64 + f]);
    }
}

// ---------------- weight transpose + gx (once) -------------------------------
__global__ void transpose_kernel(const float* __restrict__ W_ih,
                                 const float* __restrict__ W_hh) {
    int i = blockIdx.x * blockDim.x + threadIdx.x;
    if (i < 4 * D * D) {
        int r = i / D, d = i % D;
        g_WihT[d * (4 * D) + r] = W_ih[i];
        g_WhhT[d * (4 * D) + r] = W_hh[i];
    }
}
__global__ void gx_kernel(const float* __restrict__ q,
                          const float* __restrict__ b_ih,
                          const float* __restrict__ b_hh) {
    __shared__ float qs[D];
    int qi = blockIdx.x, g = threadIdx.x;
    if (g < D) qs[g] = q[qi * D + g];
    __syncthreads();
    float acc = b_ih[g] + b_hh[g];
#pragma unroll
    for (int d = 0; d < D; d++)
        acc = fmaf(qs[d], __ldg(&g_WihT[d * 256 + g]), acc);
    g_gx[qi * 256 + g] = acc;
}

// ---------------- fused attention: bf16 MMA1 + tf32 MMA2 ---------------------
// smem: H [128][64] fp32 (8192 floats) | 2 x 16384-u32 tile buffers (128KB)
__global__ void __launch_bounds__(512, 1)
attn_kernel(const float* __restrict__ q, int first) {
    extern __shared__ float sm[];
    float* Hs = sm;
    const int tid = threadIdx.x;
    const int w = tid >> 5, lane = tid & 31;
    const int g = lane >> 2, qq = lane & 3;
    const int wq = w & 7;          // query row-group
    const int jo = w >> 3;         // chunk parity group
    const int mrow = wq * 16;
    const int qbase = blockIdx.x * 128;
    const uint32_t sb = smem_u32(sm);

    // H = q (+ h_hat)
    {
        const float4* qp = (const float4*)(q + (size_t)qbase * D);
        const float4* hp = (const float4*)(g_hhat + (size_t)qbase * D);
        float4* H4 = (float4*)Hs;
        for (int i = tid; i < 2048; i += 512) {
            float4 v = qp[i];
            if (!first) {
                float4 u = hp[i];
                v.x += u.x; v.y += u.y; v.z += u.z; v.w += u.w;
            }
            H4[i] = v;
        }
    }
    __syncthreads();

    // A fragments for MMA1: bf16 hi/lo
    uint32_t ahi[16], alo[16];
    {
        int row0 = mrow + g, row1 = mrow + g + 8;
#pragma unroll
        for (int ks = 0; ks < 4; ks++) {
            int cb = ks * 16 + 2 * qq;
            bfsplit(Hs[row0 * 64 + cb],     Hs[row0 * 64 + cb + 1],
                    ahi[4 * ks + 0], alo[4 * ks + 0]);
            bfsplit(Hs[row1 * 64 + cb],     Hs[row1 * 64 + cb + 1],
                    ahi[4 * ks + 1], alo[4 * ks + 1]);
            bfsplit(Hs[row0 * 64 + cb + 8], Hs[row0 * 64 + cb + 9],
                    ahi[4 * ks + 2], alo[4 * ks + 2]);
            bfsplit(Hs[row1 * 64 + cb + 8], Hs[row1 * 64 + cb + 9],
                    ahi[4 * ks + 3], alo[4 * ks + 3]);
        }
    }

    float O[32];
#pragma unroll
    for (int i = 0; i < 32; i++) O[i] = 0.f;
    float lacc0 = 0.f, lacc1 = 0.f;

    // prefetch tiles 0,1
    {
        const char* src = (const char*)g_B + tid * 16;
        uint32_t dst = sb + 32768 + tid * 16;
#pragma unroll
        for (int i = 0; i < 8; i++) cp16(dst + i * 8192, src + i * 8192);
        CP_COMMIT();
#pragma unroll
        for (int i = 0; i < 8; i++)
            cp16(dst + 65536 + i * 8192, src + 65536 + i * 8192);
        CP_COMMIT();
    }

#pragma unroll 1
    for (int t = 0; t < NTILES; t++) {
        CP_WAIT1();
        __syncthreads();
        const uint32_t* B = (const uint32_t*)(sm + 8192) + (t & 1) * 16384;
        const float* V = (const float*)(B + 8192);

#pragma unroll 1
        for (int j = jo; j < 8; j += 2) {   // 16 support rows per chunk
            // ---- MMA1: S[16q x 16s], 3-term bf16 split
            float c0h[4] = {0, 0, 0, 0}, c0x[4] = {0, 0, 0, 0}, c0y[4] = {0, 0, 0, 0};
            float c1h[4] = {0, 0, 0, 0}, c1x[4] = {0, 0, 0, 0}, c1y[4] = {0, 0, 0, 0};
            int ioff = j * 128 + g * 16 + qq * 4;
#pragma unroll
            for (int ks = 0; ks < 4; ks++) {
                uint4 bh = *(const uint4*)(B + ks * 1024 + ioff);
                uint4 bl = *(const uint4*)(B + 4096 + ks * 1024 + ioff);
                mmabf(c0h, ahi + 4 * ks, bh.x, bh.y);
                mmabf(c0x, ahi + 4 * ks, bl.x, bl.y);
                mmabf(c0y, alo + 4 * ks, bh.x, bh.y);
                mmabf(c1h, ahi + 4 * ks, bh.z, bh.w);
                mmabf(c1x, ahi + 4 * ks, bl.z, bl.w);
                mmabf(c1y, alo + 4 * ks, bh.z, bh.w);
            }
            // ---- exp (constant shift 32 = exact softmax invariance), tf32 round
            float pA0 = tf32f(__expf(c0h[0] + c0x[0] + c0y[0] - 32.f));
            float pA1 = tf32f(__expf(c0h[1] + c0x[1] + c0y[1] - 32.f));
            float pA2 = tf32f(__expf(c0h[2] + c0x[2] + c0y[2] - 32.f));
            float pA3 = tf32f(__expf(c0h[3] + c0x[3] + c0y[3] - 32.f));
            float pB0 = tf32f(__expf(c1h[0] + c1x[0] + c1y[0] - 32.f));
            float pB1 = tf32f(__expf(c1h[1] + c1x[1] + c1y[1] - 32.f));
            float pB2 = tf32f(__expf(c1h[2] + c1x[2] + c1y[2] - 32.f));
            float pB3 = tf32f(__expf(c1h[3] + c1x[3] + c1y[3] - 32.f));
            lacc0 += (pA0 + pA1) + (pB0 + pB1);
            lacc1 += (pA2 + pA3) + (pB2 + pB3);
            // ---- MMA2: O += P @ V, tf32 single-pass (pi-permuted V, no shuffles)
            const float* Vq0 = V + (j * 8 + qq) * 128;         // h=0
            const float* Vq1 = Vq0 + 512;                      // h=1
#pragma unroll
            for (int nb = 0; nb < 8; nb++) {
                int fslot = (nb * 8 + g) ^ (qq << 2);
                float2 b0 = *(const float2*)(Vq0 + fslot * 2);
                mmatf(O + 4 * nb, pA0, pA2, pA1, pA3, b0.x, b0.y);
                float2 b1 = *(const float2*)(Vq1 + fslot * 2);
                mmatf(O + 4 * nb, pB0, pB2, pB1, pB3, b1.x, b1.y);
            }
        }
        __syncthreads();
        if (t + 2 < NTILES) {
            const char* src = (const char*)g_B + (size_t)(t + 2) * 65536 + tid * 16;
            uint32_t dst = sb + 32768 + (t & 1) * 65536 + tid * 16;
#pragma unroll
            for (int i = 0; i < 8; i++) cp16(dst + i * 8192, src + i * 8192);
        }
        CP_COMMIT();
    }

    // quad-reduce row sums
    lacc0 += __shfl_xor_sync(0xffffffffu, lacc0, 1);
    lacc0 += __shfl_xor_sync(0xffffffffu, lacc0, 2);
    lacc1 += __shfl_xor_sync(0xffffffffu, lacc1, 1);
    lacc1 += __shfl_xor_sync(0xffffffffu, lacc1, 2);

    // cross-group combine via smem (alias tile-buffer region)
    CP_WAIT0();
    __syncthreads();
    float* Ox = sm + 8192;          // [128][64]
    float* lx = sm + 8192 + 8192;   // [128]
    int row0 = mrow + g, row1 = row0 + 8;
    if (jo == 1) {
#pragma unroll
        for (int nb = 0; nb < 8; nb++) {
            int c = nb * 8 + 2 * qq;
            *(float2*)(Ox + row0 * 64 + c) = make_float2(O[4 * nb + 0], O[4 * nb + 1]);
            *(float2*)(Ox + row1 * 64 + c) = make_float2(O[4 * nb + 2], O[4 * nb + 3]);
        }
        if (qq == 0) { lx[row0] = lacc0; lx[row1] = lacc1; }
    }
    __syncthreads();
    if (jo == 0) {
        float inv0 = 1.f / (lacc0 + lx[row0]);
        float inv1 = 1.f / (lacc1 + lx[row1]);
        float* z0 = g_z + (size_t)(qbase + row0) * D;
        float* z1 = g_z + (size_t)(qbase + row1) * D;
#pragma unroll
        for (int nb = 0; nb < 8; nb++) {
            int c = nb * 8 + 2 * qq;
            float2 ob0 = *(const float2*)(Ox + row0 * 64 + c);
            float2 ob1 = *(const float2*)(Ox + row1 * 64 + c);
            float2 v0, v1;
            v0.x = Hs[row0 * 64 + c]     + (O[4 * nb + 0] + ob0.x) * inv0;
            v0.y = Hs[row0 * 64 + c + 1] + (O[4 * nb + 1] + ob0.y) * inv0;
            v1.x = Hs[row1 * 64 + c]     + (O[4 * nb + 2] + ob1.x) * inv1;
            v1.y = Hs[row1 * 64 + c + 1] + (O[4 * nb + 3] + ob1.y) * inv1;
            *(float2*)(z0 + c) = v0;
            *(float2*)(z1 + c) = v1;
        }
    }
}

// ---------------- LSTM cell --------------------------------------------------
__global__ void lstm_kernel(const float* __restrict__ q, float* __restrict__ out,
                            int first, int last) {
    __shared__ float zs[4][D];
    int ql = threadIdx.x >> 6;
    int u = threadIdx.x & 63;
    int qi = blockIdx.x * 4 + ql;

    zs[ql][u] = g_z[qi * D + u];
    __syncthreads();

    const float* gxp = g_gx + qi * 256;
    float gi = gxp[u];
    float gf = gxp[64 + u];
    float gg = gxp[128 + u];
    float go = gxp[192 + u];

#pragma unroll 8
    for (int d = 0; d < D; d++) {
        float zd = zs[ql][d];
        const float* wp = g_WhhT + d * 256;
        gi = fmaf(zd, __ldg(wp + u), gi);
        gf = fmaf(zd, __ldg(wp + 64 + u), gf);
        gg = fmaf(zd, __ldg(wp + 128 + u), gg);
        go = fmaf(zd, __ldg(wp + 192 + u), go);
    }

    float c_old = first ? 0.f : g_c[qi * D + u];
    float cn = sigf(gf) * c_old + sigf(gi) * tanhf(gg);
    float hn = sigf(go) * tanhf(cn);
    g_c[qi * D + u] = cn;
    g_hhat[qi * D + u] = hn;
    if (last) out[qi * D + u] = hn + q[qi * D + u];
}

// ---------------- launch ------------------------------------------------------
extern "C" void kernel_launch(void* const* d_in, const int* in_sizes, int n_in,
                              void* d_out, int out_size) {
    const float* support = (const float*)d_in[0];
    const float* queries = (const float*)d_in[1];
    const float* W_ih    = (const float*)d_in[2];
    const float* W_hh    = (const float*)d_in[3];
    const float* b_ih    = (const float*)d_in[4];
    const float* b_hh    = (const float*)d_in[5];
    float* out = (float*)d_out;

    const int smem_bytes = 8192 * 4 + 2 * 16384 * 4;   // 163840
    cudaFuncSetAttribute(attn_kernel, cudaFuncAttributeMaxDynamicSharedMemorySize,
                         smem_bytes);

    prep_kernel<<<NTILES, 256>>>(support);
    transpose_kernel<<<(4 * D * D + 255) / 256, 256>>>(W_ih, W_hh);
    gx_kernel<<<NQ, 256>>>(queries, b_ih, b_hh);

    for (int step = 0; step < STEPS; step++) {
        int first = (step == 0);
        int last = (step == STEPS - 1);
        attn_kernel<<<NCTA, 512, smem_bytes>>>(queries, first);
        lstm_kernel<<<NQ / 4, 256>>>(queries, out, first, last);
    }
}

// round 8
// speedup vs baseline: 2.3018x; 1.0899x over previous
#include <cuda_runtime.h>
#include <cuda_bf16.h>
#include <cstdint>
#include <math.h>

#define NQ 16384
#define NS 8192
#define D 64
#define NTILES 64          // support tiles of 128 rows
#define STEPS 10
#define NCTA (NQ / 128)    // 128 CTAs, 16 warps each

// ---------------- device globals (no allocations allowed) -------------------
__device__ float g_hhat[NQ * D];          // h = h_hat + q (pre-added)
__device__ float g_c[NQ * D];
__device__ float g_gx[NQ * 4 * D];        // [q][u][gate i,f,g,o]
__device__ float g_WihT[D * 4 * D];       // [d][row]
__device__ float g_Whh4[D * D * 4];       // [d][u][gate]
// Per tile (16384 u32 = 64KB):
//  I1: u32[term2][ks4][j8][g8][qq4][vec4]          (8192 u32)
//      vec = (b0@r0, b1@r0, b0@r8, b1@r8), r0=16j+g, r8=r0+8,
//      b0 = bf16x2 features (16ks+2qq, +1), b1 = (16ks+8+2qq, +1)
//  V : f32[j8][h2][qq4][fslot64][pr2] at +8192     (8192 f32)
//      f = fslot ^ (qq<<2); pr 0/1 -> support row 16j+8h+2qq+pr (tf32)
__device__ __align__(16) uint32_t g_B[(size_t)NTILES * 16384];

// ---------------- helpers ----------------------------------------------------
__device__ __forceinline__ uint32_t smem_u32(const void* p) {
    uint32_t a;
    asm("{ .reg .u64 t; cvta.to.shared.u64 t, %1; cvt.u32.u64 %0, t; }"
        : "=r"(a) : "l"(p));
    return a;
}
__device__ __forceinline__ void cp16(uint32_t saddr, const void* g) {
    asm volatile("cp.async.cg.shared.global [%0], [%1], 16;"
                 :: "r"(saddr), "l"(g) : "memory");
}
#define CP_COMMIT() asm volatile("cp.async.commit_group;" ::: "memory")
#define CP_WAIT1()  asm volatile("cp.async.wait_group 1;" ::: "memory")
#define CP_WAIT0()  asm volatile("cp.async.wait_group 0;" ::: "memory")

__device__ __forceinline__ float tf32f(float v) {
    float r;
    asm("cvt.rna.tf32.f32 %0, %1;" : "=f"(r) : "f"(v));
    return r;
}
__device__ __forceinline__ uint32_t bfpack(float lo, float hi) {
    __nv_bfloat162 t = __floats2bfloat162_rn(lo, hi);
    return *reinterpret_cast<uint32_t*>(&t);
}
__device__ __forceinline__ void bfsplit(float v0, float v1,
                                        uint32_t& hi, uint32_t& lo) {
    hi = bfpack(v0, v1);
    float h0 = __uint_as_float(hi << 16);
    float h1 = __uint_as_float(hi & 0xffff0000u);
    lo = bfpack(v0 - h0, v1 - h1);
}
__device__ __forceinline__ void mmabf(float* c, const uint32_t* a,
                                      uint32_t b0, uint32_t b1) {
    asm volatile(
        "mma.sync.aligned.m16n8k16.row.col.f32.bf16.bf16.f32 "
        "{%0,%1,%2,%3}, {%4,%5,%6,%7}, {%8,%9}, {%0,%1,%2,%3};"
        : "+f"(c[0]), "+f"(c[1]), "+f"(c[2]), "+f"(c[3])
        : "r"(a[0]), "r"(a[1]), "r"(a[2]), "r"(a[3]), "r"(b0), "r"(b1));
}
__device__ __forceinline__ void mmatf(float* c, float a0, float a1, float a2,
                                      float a3, float b0, float b1) {
    asm volatile(
        "mma.sync.aligned.m16n8k8.row.col.f32.tf32.tf32.f32 "
        "{%0,%1,%2,%3}, {%4,%5,%6,%7}, {%8,%9}, {%0,%1,%2,%3};"
        : "+f"(c[0]), "+f"(c[1]), "+f"(c[2]), "+f"(c[3])
        : "r"(__float_as_uint(a0)), "r"(__float_as_uint(a1)),
          "r"(__float_as_uint(a2)), "r"(__float_as_uint(a3)),
          "r"(__float_as_uint(b0)), "r"(__float_as_uint(b1)));
}
__device__ __forceinline__ float sigf(float x) { return 1.f / (1.f + __expf(-x)); }

// ---------------- prep: support images --------------------------------------
__global__ void prep_kernel(const float* __restrict__ support) {
    int t = blockIdx.x;
    const float* s = support + (size_t)t * 128 * D;
    uint32_t* dst = g_B + (size_t)t * 16384;
    for (int i = threadIdx.x; i < 4096; i += 256) {
        int vec = i & 3, qq = (i >> 2) & 3, g = (i >> 4) & 7;
        int j = (i >> 7) & 7, ks = (i >> 10) & 3;
        int r = 16 * j + g + ((vec & 2) ? 8 : 0);
        int f0 = ks * 16 + ((vec & 1) ? 8 : 0) + 2 * qq;
        uint32_t hi, lo;
        bfsplit(s[r * 64 + f0], s[r * 64 + f0 + 1], hi, lo);
        dst[i] = hi;
        dst[4096 + i] = lo;
    }
    float* vd = (float*)(dst + 8192);
    for (int i = threadIdx.x; i < 8192; i += 256) {
        int pr = i & 1, fslot = (i >> 1) & 63, qq = (i >> 7) & 3;
        int h = (i >> 9) & 1, j = (i >> 10) & 7;
        int f = fslot ^ (qq << 2);
        int row = 16 * j + 8 * h + 2 * qq + pr;
        vd[i] = tf32f(s[row * 64 + f]);
    }
}

// ---------------- weight prep + gx (once) ------------------------------------
__global__ void transpose_kernel(const float* __restrict__ W_ih,
                                 const float* __restrict__ W_hh) {
    int i = blockIdx.x * blockDim.x + threadIdx.x;
    if (i < 256 * 64) {
        int r = i / D, d = i % D;
        g_WihT[d * 256 + r] = W_ih[i];
        g_Whh4[(d * 64 + (r & 63)) * 4 + (r >> 6)] = W_hh[i];
    }
}
__global__ void gx_kernel(const float* __restrict__ q,
                          const float* __restrict__ b_ih,
                          const float* __restrict__ b_hh) {
    __shared__ float qs[D];
    int qi = blockIdx.x, g = threadIdx.x;
    if (g < D) qs[g] = q[qi * D + g];
    __syncthreads();
    float acc = b_ih[g] + b_hh[g];
#pragma unroll
    for (int d = 0; d < D; d++)
        acc = fmaf(qs[d], __ldg(&g_WihT[d * 256 + g]), acc);
    g_gx[qi * 256 + (g & 63) * 4 + (g >> 6)] = acc;
}

// ---------------- fused attention + LSTM tail --------------------------------
// smem: H [128][64] fp32 (8192 floats) | 2 x 16384-u32 tile buffers (128KB)
__global__ void __launch_bounds__(512, 1)
attn_kernel(const float* __restrict__ q, float* __restrict__ out,
            int first, int last) {
    extern __shared__ float sm[];
    float* Hs = sm;
    const int tid = threadIdx.x;
    const int w = tid >> 5, lane = tid & 31;
    const int g = lane >> 2, qq = lane & 3;
    const int wq = w & 7;          // query row-group
    const int jo = w >> 3;         // chunk parity group
    const int mrow = wq * 16;
    const int qbase = blockIdx.x * 128;
    const uint32_t sb = smem_u32(sm);

    // H (pre-added h_hat + q is stored in g_hhat)
    {
        const float4* src = first
            ? (const float4*)(q + (size_t)qbase * D)
            : (const float4*)(g_hhat + (size_t)qbase * D);
        float4* H4 = (float4*)Hs;
        for (int i = tid; i < 2048; i += 512) H4[i] = src[i];
    }
    __syncthreads();

    // A fragments for MMA1: bf16 hi/lo
    uint32_t ahi[16], alo[16];
    {
        int row0 = mrow + g, row1 = mrow + g + 8;
#pragma unroll
        for (int ks = 0; ks < 4; ks++) {
            int cb = ks * 16 + 2 * qq;
            bfsplit(Hs[row0 * 64 + cb],     Hs[row0 * 64 + cb + 1],
                    ahi[4 * ks + 0], alo[4 * ks + 0]);
            bfsplit(Hs[row1 * 64 + cb],     Hs[row1 * 64 + cb + 1],
                    ahi[4 * ks + 1], alo[4 * ks + 1]);
            bfsplit(Hs[row0 * 64 + cb + 8], Hs[row0 * 64 + cb + 9],
                    ahi[4 * ks + 2], alo[4 * ks + 2]);
            bfsplit(Hs[row1 * 64 + cb + 8], Hs[row1 * 64 + cb + 9],
                    ahi[4 * ks + 3], alo[4 * ks + 3]);
        }
    }

    float O[32];
#pragma unroll
    for (int i = 0; i < 32; i++) O[i] = 0.f;
    float lacc0 = 0.f, lacc1 = 0.f;

    // prefetch tiles 0,1
    {
        const char* src = (const char*)g_B + tid * 16;
        uint32_t dst = sb + 32768 + tid * 16;
#pragma unroll
        for (int i = 0; i < 8; i++) cp16(dst + i * 8192, src + i * 8192);
        CP_COMMIT();
#pragma unroll
        for (int i = 0; i < 8; i++)
            cp16(dst + 65536 + i * 8192, src + 65536 + i * 8192);
        CP_COMMIT();
    }

    // fslot per nb is chunk-invariant
    int fslot[8];
#pragma unroll
    for (int nb = 0; nb < 8; nb++) fslot[nb] = ((nb * 8 + g) ^ (qq << 2)) * 2;

#pragma unroll 1
    for (int t = 0; t < NTILES; t++) {
        CP_WAIT1();
        __syncthreads();
        const uint32_t* B = (const uint32_t*)(sm + 8192) + (t & 1) * 16384;
        const float* V = (const float*)(B + 8192);

        float pA0, pA1, pA2, pA3, pB0, pB1, pB2, pB3;
        const float* Vp0;
        const float* Vp1;

#pragma unroll
        for (int jc = 0; jc < 4; jc++) {
            int j = jo + 2 * jc;
            // ---- MMA1: S[16q x 16s], 3-term bf16 split (corrections merged)
            float c0h[4] = {0, 0, 0, 0}, c0c[4] = {0, 0, 0, 0};
            float c1h[4] = {0, 0, 0, 0}, c1c[4] = {0, 0, 0, 0};
            int ioff = j * 128 + g * 16 + qq * 4;
#pragma unroll
            for (int ks = 0; ks < 4; ks++) {
                uint4 bh = *(const uint4*)(B + ks * 1024 + ioff);
                uint4 bl = *(const uint4*)(B + 4096 + ks * 1024 + ioff);
                mmabf(c0h, ahi + 4 * ks, bh.x, bh.y);
                mmabf(c0c, ahi + 4 * ks, bl.x, bl.y);
                mmabf(c0c, alo + 4 * ks, bh.x, bh.y);
                mmabf(c1h, ahi + 4 * ks, bh.z, bh.w);
                mmabf(c1c, ahi + 4 * ks, bl.z, bl.w);
                mmabf(c1c, alo + 4 * ks, bh.z, bh.w);
            }
            // ---- MMA2 for previous chunk (independent of MMA1 above):
            // fills the pipe while MMA1 results cook
            if (jc > 0) {
#pragma unroll
                for (int nb = 0; nb < 8; nb++) {
                    float2 b0 = *(const float2*)(Vp0 + fslot[nb]);
                    mmatf(O + 4 * nb, pA0, pA2, pA1, pA3, b0.x, b0.y);
                    float2 b1 = *(const float2*)(Vp1 + fslot[nb]);
                    mmatf(O + 4 * nb, pB0, pB2, pB1, pB3, b1.x, b1.y);
                }
            }
            // ---- exp (constant shift 32 = exact softmax invariance), tf32 round
            pA0 = tf32f(__expf(c0h[0] + c0c[0] - 32.f));
            pA1 = tf32f(__expf(c0h[1] + c0c[1] - 32.f));
            pA2 = tf32f(__expf(c0h[2] + c0c[2] - 32.f));
            pA3 = tf32f(__expf(c0h[3] + c0c[3] - 32.f));
            pB0 = tf32f(__expf(c1h[0] + c1c[0] - 32.f));
            pB1 = tf32f(__expf(c1h[1] + c1c[1] - 32.f));
            pB2 = tf32f(__expf(c1h[2] + c1c[2] - 32.f));
            pB3 = tf32f(__expf(c1h[3] + c1c[3] - 32.f));
            lacc0 += (pA0 + pA1) + (pB0 + pB1);
            lacc1 += (pA2 + pA3) + (pB2 + pB3);
            Vp0 = V + (j * 8 + qq) * 128;
            Vp1 = Vp0 + 512;
        }
        // ---- drain: MMA2 of last chunk (before buffer reuse)
#pragma unroll
        for (int nb = 0; nb < 8; nb++) {
            float2 b0 = *(const float2*)(Vp0 + fslot[nb]);
            mmatf(O + 4 * nb, pA0, pA2, pA1, pA3, b0.x, b0.y);
            float2 b1 = *(const float2*)(Vp1 + fslot[nb]);
            mmatf(O + 4 * nb, pB0, pB2, pB1, pB3, b1.x, b1.y);
        }
        __syncthreads();
        if (t + 2 < NTILES) {
            const char* src = (const char*)g_B + (size_t)(t + 2) * 65536 + tid * 16;
            uint32_t dst = sb + 32768 + (t & 1) * 65536 + tid * 16;
#pragma unroll
            for (int i = 0; i < 8; i++) cp16(dst + i * 8192, src + i * 8192);
        }
        CP_COMMIT();
    }

    // quad-reduce row sums
    lacc0 += __shfl_xor_sync(0xffffffffu, lacc0, 1);
    lacc0 += __shfl_xor_sync(0xffffffffu, lacc0, 2);
    lacc1 += __shfl_xor_sync(0xffffffffu, lacc1, 1);
    lacc1 += __shfl_xor_sync(0xffffffffu, lacc1, 2);

    // cross-group combine via smem (alias tile-buffer region); z -> Hs in place
    CP_WAIT0();
    __syncthreads();
    float* Ox = sm + 8192;          // [128][64]
    float* lx = sm + 8192 + 8192;   // [128]
    int row0 = mrow + g, row1 = row0 + 8;
    if (jo == 1) {
#pragma unroll
        for (int nb = 0; nb < 8; nb++) {
            int c = nb * 8 + 2 * qq;
            *(float2*)(Ox + row0 * 64 + c) = make_float2(O[4 * nb + 0], O[4 * nb + 1]);
            *(float2*)(Ox + row1 * 64 + c) = make_float2(O[4 * nb + 2], O[4 * nb + 3]);
        }
        if (qq == 0) { lx[row0] = lacc0; lx[row1] = lacc1; }
    }
    __syncthreads();
    if (jo == 0) {
        float inv0 = 1.f / (lacc0 + lx[row0]);
        float inv1 = 1.f / (lacc1 + lx[row1]);
#pragma unroll
        for (int nb = 0; nb < 8; nb++) {
            int c = nb * 8 + 2 * qq;
            float2 ob0 = *(const float2*)(Ox + row0 * 64 + c);
            float2 ob1 = *(const float2*)(Ox + row1 * 64 + c);
            float z00 = Hs[row0 * 64 + c]     + (O[4 * nb + 0] + ob0.x) * inv0;
            float z01 = Hs[row0 * 64 + c + 1] + (O[4 * nb + 1] + ob0.y) * inv0;
            float z10 = Hs[row1 * 64 + c]     + (O[4 * nb + 2] + ob1.x) * inv1;
            float z11 = Hs[row1 * 64 + c + 1] + (O[4 * nb + 3] + ob1.y) * inv1;
            *(float2*)(Hs + row0 * 64 + c) = make_float2(z00, z01);
            *(float2*)(Hs + row1 * 64 + c) = make_float2(z10, z11);
        }
    }
    __syncthreads();

    // ---- LSTM tail: warp w owns queries w*8..w*8+7; units lane, lane+32
    {
        const int w8 = w * 8;
        const int uA = lane, uB = lane + 32;
        float4 accA[8], accB[8];
#pragma unroll
        for (int qi = 0; qi < 8; qi++) {
            int gq = qbase + w8 + qi;
            accA[qi] = __ldg((const float4*)&g_gx[(size_t)gq * 256 + uA * 4]);
            accB[qi] = __ldg((const float4*)&g_gx[(size_t)gq * 256 + uB * 4]);
        }
#pragma unroll 2
        for (int d = 0; d < 64; d++) {
            float4 wA = __ldg((const float4*)&g_Whh4[(d * 64 + uA) * 4]);
            float4 wB = __ldg((const float4*)&g_Whh4[(d * 64 + uB) * 4]);
#pragma unroll
            for (int qi = 0; qi < 8; qi++) {
                float zd = Hs[(w8 + qi) * 64 + d];
                accA[qi].x = fmaf(zd, wA.x, accA[qi].x);
                accA[qi].y = fmaf(zd, wA.y, accA[qi].y);
                accA[qi].z = fmaf(zd, wA.z, accA[qi].z);
                accA[qi].w = fmaf(zd, wA.w, accA[qi].w);
                accB[qi].x = fmaf(zd, wB.x, accB[qi].x);
                accB[qi].y = fmaf(zd, wB.y, accB[qi].y);
                accB[qi].z = fmaf(zd, wB.z, accB[qi].z);
                accB[qi].w = fmaf(zd, wB.w, accB[qi].w);
            }
        }
#pragma unroll
        for (int qi = 0; qi < 8; qi++) {
            int row = w8 + qi;
            int gq = qbase + row;
            {
                float4 a = accA[qi];
                float co = first ? 0.f : g_c[(size_t)gq * 64 + uA];
                float cn = sigf(a.y) * co + sigf(a.x) * tanhf(a.z);
                float hn = sigf(a.w) * tanhf(cn);
                g_c[(size_t)gq * 64 + uA] = cn;
                float hv = hn + __ldg(&q[(size_t)gq * 64 + uA]);
                if (last) out[(size_t)gq * 64 + uA] = hv;
                else g_hhat[(size_t)gq * 64 + uA] = hv;
            }
            {
                float4 a = accB[qi];
                float co = first ? 0.f : g_c[(size_t)gq * 64 + uB];
                float cn = sigf(a.y) * co + sigf(a.x) * tanhf(a.z);
                float hn = sigf(a.w) * tanhf(cn);
                g_c[(size_t)gq * 64 + uB] = cn;
                float hv = hn + __ldg(&q[(size_t)gq * 64 + uB]);
                if (last) out[(size_t)gq * 64 + uB] = hv;
                else g_hhat[(size_t)gq * 64 + uB] = hv;
            }
        }
    }
}

// ---------------- launch ------------------------------------------------------
extern "C" void kernel_launch(void* const* d_in, const int* in_sizes, int n_in,
                              void* d_out, int out_size) {
    const float* support = (const float*)d_in[0];
    const float* queries = (const float*)d_in[1];
    const float* W_ih    = (const float*)d_in[2];
    const float* W_hh    = (const float*)d_in[3];
    const float* b_ih    = (const float*)d_in[4];
    const float* b_hh    = (const float*)d_in[5];
    float* out = (float*)d_out;

    const int smem_bytes = 8192 * 4 + 2 * 16384 * 4;   // 163840
    cudaFuncSetAttribute(attn_kernel, cudaFuncAttributeMaxDynamicSharedMemorySize,
                         smem_bytes);

    prep_kernel<<<NTILES, 256>>>(support);
    transpose_kernel<<<(256 * 64 + 255) / 256, 256>>>(W_ih, W_hh);
    gx_kernel<<<NQ, 256>>>(queries, b_ih, b_hh);

    for (int step = 0; step < STEPS; step++) {
        int first = (step == 0);
        int last = (step == STEPS - 1);
        attn_kernel<<<NCTA, 512, smem_bytes>>>(queries, out, first, last);
    }
}